// round 1
// baseline (speedup 1.0000x reference)
#include <cuda_runtime.h>

// SpectralGatingNetwork: y = irfft2(rfft2(x, ortho) * wc, ortho)
// x: (64, 768, 64, 64) f32; complex_weight: (64, 33, 768, 2) f32; out like x.
//
// One CTA handles one (batch b, channel pair c0,c0+1): packs the two real
// images as real/imag of one complex 64x64 plane. Full complex 2D FFT
// (two radix-8 stages per 64-pt transform, 8 lanes per transform, shfl-based
// 8x8 register transpose between stages), Hermitian-split gate (with the
// w=0/32 columns' gates symmetrized so the gated spectrum is exactly
// Hermitian), inverse 2D FFT; real part -> c0, imag part -> c1.
// Ortho norm (1/sqrt(4096) fwd * 1/sqrt(4096) inv) folded into gate as 1/4096.

#define CC 768

__device__ __forceinline__ float2 cadd(float2 a, float2 b){ return make_float2(a.x+b.x, a.y+b.y); }
__device__ __forceinline__ float2 csub(float2 a, float2 b){ return make_float2(a.x-b.x, a.y-b.y); }
__device__ __forceinline__ float2 cmul(float2 a, float2 b){
    return make_float2(fmaf(a.x, b.x, -a.y*b.y), fmaf(a.x, b.y, a.y*b.x));
}

// multiply by i*S  (S = -1 forward, +1 inverse)
template<int S>
__device__ __forceinline__ float2 mul_iS(float2 a){
    return (S > 0) ? make_float2(-a.y, a.x) : make_float2(a.y, -a.x);
}

// 8-point DFT, y[k] = sum_n x[n] e^{S*2pi*i*n*k/8}, in/out natural order.
template<int S>
__device__ __forceinline__ void dft8(float2 a[8]){
    const float r  = 0.70710678118654752440f;
    const float sf = (float)S;
    float2 e0 = cadd(a[0], a[4]), e1 = csub(a[0], a[4]);
    float2 e2 = cadd(a[2], a[6]), e3 = mul_iS<S>(csub(a[2], a[6]));
    float2 E0 = cadd(e0, e2), E2 = csub(e0, e2);
    float2 E1 = cadd(e1, e3), E3 = csub(e1, e3);
    float2 o0 = cadd(a[1], a[5]), o1 = csub(a[1], a[5]);
    float2 o2 = cadd(a[3], a[7]), o3 = mul_iS<S>(csub(a[3], a[7]));
    float2 O0 = cadd(o0, o2), O2 = csub(o0, o2);
    float2 O1 = cadd(o1, o3), O3 = csub(o1, o3);
    // W8^1 = (r, S r), W8^2 = iS, W8^3 = (-r, S r)
    float2 t1 = make_float2(r * (O1.x - sf * O1.y), r * (O1.y + sf * O1.x));
    float2 t2 = mul_iS<S>(O2);
    float2 t3 = make_float2(-r * (O3.x + sf * O3.y), r * (sf * O3.x - O3.y));
    a[0] = cadd(E0, O0); a[4] = csub(E0, O0);
    a[1] = cadd(E1, t1); a[5] = csub(E1, t1);
    a[2] = cadd(E2, t2); a[6] = csub(E2, t2);
    a[3] = cadd(E3, t3); a[7] = csub(E3, t3);
}

// 8x8 transpose across the 8 lanes of a lane-octet (recursive block swap).
__device__ __forceinline__ void transpose8(float2 a[8], int t){
    #pragma unroll
    for (int m = 1; m < 8; m <<= 1){
        bool hi = (t & m) != 0;
        #pragma unroll
        for (int j0 = 0; j0 < 8; ++j0){
            if ((j0 & m) == 0){
                const int j1 = j0 | m;
                float2 send = hi ? a[j0] : a[j1];
                float2 rcv;
                rcv.x = __shfl_xor_sync(0xffffffffu, send.x, m);
                rcv.y = __shfl_xor_sync(0xffffffffu, send.y, m);
                if (hi) a[j0] = rcv; else a[j1] = rcv;
            }
        }
    }
}

// 64-pt DFT across 8 lanes (t = lane%8). Input: a[j] = x[t + 8j].
// Output: a[j] = X[8j + t].
template<int S>
__device__ __forceinline__ void fft64(float2 a[8], int t){
    dft8<S>(a);                 // over n2
    float sn, cs;               // base twiddle e^{S*2pi*i*t/64}
    sincospif((float)(S * t) * (1.0f / 32.0f), &sn, &cs);
    float2 wb = make_float2(cs, sn);
    float2 tw = wb;
    #pragma unroll
    for (int k = 1; k < 8; ++k){
        a[k] = cmul(a[k], tw);  // * W64^{t*k}
        tw   = cmul(tw, wb);
    }
    transpose8(a, t);           // lane now indexes k2
    dft8<S>(a);                 // over n1
}

// Swizzled shared index: conflict-free for both row-major and col-major
// octet-strided access patterns used below.
__device__ __forceinline__ int sidx(int h, int w){
    return h * 64 + (w ^ (9 * (h & 7)));
}

__global__ void __launch_bounds__(256)
sgn_kernel(const float* __restrict__ x, const float* __restrict__ cw,
           float* __restrict__ out){
    __shared__ float2 tile[64 * 64];

    const int tid = threadIdx.x;
    const int t   = tid & 7;      // lane-in-octet
    const int g   = tid >> 3;     // octet index 0..31
    const int cpair = blockIdx.x; // 0..383
    const int b     = blockIdx.y; // 0..63
    const int c0    = cpair * 2;

    const float* xa = x + ((size_t)(b * CC + c0)) * 4096;
    const float* xb = xa + 4096;

    // ---- forward row FFTs (gmem -> smem) ----
    #pragma unroll
    for (int it = 0; it < 2; ++it){
        const int row = g + 32 * it;
        float2 a[8];
        #pragma unroll
        for (int j = 0; j < 8; ++j){
            const int w = t + 8 * j;
            a[j] = make_float2(xa[row * 64 + w], xb[row * 64 + w]);
        }
        fft64<-1>(a, t);
        #pragma unroll
        for (int j = 0; j < 8; ++j) tile[sidx(row, 8 * j + t)] = a[j];
    }
    __syncthreads();

    // ---- forward column FFTs ----
    #pragma unroll
    for (int it = 0; it < 2; ++it){
        const int col = g + 32 * it;
        float2 a[8];
        #pragma unroll
        for (int j = 0; j < 8; ++j) a[j] = tile[sidx(t + 8 * j, col)];
        fft64<-1>(a, t);
        #pragma unroll
        for (int j = 0; j < 8; ++j) tile[sidx(8 * j + t, col)] = a[j];
    }
    __syncthreads();

    // ---- Hermitian-split gate ----
    // canonical points: (h, w) with 1<=w<=31 (all h), or w in {0,32} with h<=32.
    const float sc = 0.5f * (1.0f / 4096.0f);
    for (int k = 0; k < 9; ++k){
        const int i = tid + 256 * k;
        if (i >= 2112) break;
        const int w = i % 33;
        const int h = i / 33;
        const bool edge = (w == 0) || (w == 32);
        if (edge && h > 32) continue;
        const int hb = (64 - h) & 63;
        const int wb = (64 - w) & 63;

        const float2 Z1 = tile[sidx(h,  w )];
        const float2 Z2 = tile[sidx(hb, wb)];

        const float4 wA = *reinterpret_cast<const float4*>(
            cw + ((size_t)(h * 33 + w) * CC + c0) * 2);
        float2 Ga = make_float2(wA.x, wA.y);
        float2 Gb = make_float2(wA.z, wA.w);
        if (edge){
            // symmetrize gate on w=0/32 columns: G~ = (wc[h] + conj(wc[hb]))/2
            const float4 wB = *reinterpret_cast<const float4*>(
                cw + ((size_t)(hb * 33 + w) * CC + c0) * 2);
            Ga = make_float2(0.5f * (Ga.x + wB.x), 0.5f * (Ga.y - wB.y));
            Gb = make_float2(0.5f * (Gb.x + wB.z), 0.5f * (Gb.y - wB.w));
        }

        // A = Xa*sc, Bv = Xb*sc (Hermitian split of packed spectrum)
        const float2 A  = make_float2(sc * (Z1.x + Z2.x), sc * (Z1.y - Z2.y));
        const float2 Bv = make_float2(sc * (Z1.y + Z2.y), sc * (Z2.x - Z1.x));
        const float2 P = cmul(A,  Ga);
        const float2 Q = cmul(Bv, Gb);
        // Z1' = P + iQ ; Z2' = conj(P) + i conj(Q)
        tile[sidx(h,  w )] = make_float2(P.x - Q.y, P.y + Q.x);
        tile[sidx(hb, wb)] = make_float2(P.x + Q.y, Q.x - P.y);
    }
    __syncthreads();

    // ---- inverse column FFTs ----
    #pragma unroll
    for (int it = 0; it < 2; ++it){
        const int col = g + 32 * it;
        float2 a[8];
        #pragma unroll
        for (int j = 0; j < 8; ++j) a[j] = tile[sidx(t + 8 * j, col)];
        fft64<1>(a, t);
        #pragma unroll
        for (int j = 0; j < 8; ++j) tile[sidx(8 * j + t, col)] = a[j];
    }
    __syncthreads();

    // ---- inverse row FFTs (smem -> gmem) ----
    float* oa = out + ((size_t)(b * CC + c0)) * 4096;
    float* ob = oa + 4096;
    #pragma unroll
    for (int it = 0; it < 2; ++it){
        const int row = g + 32 * it;
        float2 a[8];
        #pragma unroll
        for (int j = 0; j < 8; ++j) a[j] = tile[sidx(row, t + 8 * j)];
        fft64<1>(a, t);
        #pragma unroll
        for (int j = 0; j < 8; ++j){
            const int w = 8 * j + t;
            oa[row * 64 + w] = a[j].x;
            ob[row * 64 + w] = a[j].y;
        }
    }
}

extern "C" void kernel_launch(void* const* d_in, const int* in_sizes, int n_in,
                              void* d_out, int out_size){
    const float* x  = (const float*)d_in[0];
    const float* cw = (const float*)d_in[1];
    float* out = (float*)d_out;
    dim3 grid(CC / 2, 64);   // (384 channel-pairs, 64 batches)
    sgn_kernel<<<grid, 256>>>(x, cw, out);
}